// round 1
// baseline (speedup 1.0000x reference)
#include <cuda_runtime.h>
#include <math.h>

#define CH 128
#define NMAX 100000

// ---------------- scratch (no allocations allowed) ----------------
__device__ float g_dinv[NMAX];
__device__ float g_h1[(size_t)NMAX * CH];   // GEMM output / normalized hidden
__device__ float g_agg[(size_t)NMAX * CH];  // aggregation buffer / GEMM2 output

// ---------------- vector red helper (sm_90+) ----------------
__device__ __forceinline__ void red_add_v4(float* addr, float4 v) {
    asm volatile("red.global.add.v4.f32 [%0], {%1, %2, %3, %4};"
                 :: "l"(addr), "f"(v.x), "f"(v.y), "f"(v.z), "f"(v.w)
                 : "memory");
}

// ---------------- degree / dinv ----------------
__global__ void k_deg_init(int n) {
    int i = blockIdx.x * blockDim.x + threadIdx.x;
    if (i < n) g_dinv[i] = 1.0f;  // self loop
}

__global__ void k_deg_count(const int* __restrict__ dst, int E) {
    int i = blockIdx.x * blockDim.x + threadIdx.x;
    if (i < E) atomicAdd(&g_dinv[dst[i]], 1.0f);
}

__global__ void k_dinv(int n) {
    int i = blockIdx.x * blockDim.x + threadIdx.x;
    if (i < n) g_dinv[i] = rsqrtf(g_dinv[i]);
}

// ---------------- SGEMM: Y[n x 128] = X[n x 128] @ W[128 x 128] ----------------
// 128x128 block tile, 256 threads, 8x8 register micro-tile, k-step 8.
// If Wb != nullptr: W = [Wa (128x64) | Wb (128x64)] concatenated column-wise.
__global__ __launch_bounds__(256)
void k_gemm(const float* __restrict__ X,
            const float* __restrict__ Wa,
            const float* __restrict__ Wb,
            float* __restrict__ Y, int n) {
    __shared__ float sX[8][128];
    __shared__ float sW[8][128];

    int tid  = threadIdx.x;
    int tcol = tid & 15;    // 16 col groups of 8
    int trow = tid >> 4;    // 16 row groups of 8
    int row0 = blockIdx.x * 128;

    float acc[8][8];
#pragma unroll
    for (int i = 0; i < 8; i++)
#pragma unroll
        for (int j = 0; j < 8; j++) acc[i][j] = 0.0f;

    for (int k0 = 0; k0 < 128; k0 += 8) {
        // load X tile (128 rows x 8 k), transposed into sX[kk][row]
        {
            int r    = tid >> 1;
            int half = tid & 1;
            int row  = row0 + r;
            float4 v = make_float4(0.f, 0.f, 0.f, 0.f);
            if (row < n)
                v = *(const float4*)&X[(size_t)row * CH + k0 + half * 4];
            sX[half * 4 + 0][r] = v.x;
            sX[half * 4 + 1][r] = v.y;
            sX[half * 4 + 2][r] = v.z;
            sX[half * 4 + 3][r] = v.w;
        }
        // load W tile (8 k x 128 cols)
        {
            int idx = tid * 4;
            int kk  = idx >> 7;
            int c   = idx & 127;
            if (Wb == nullptr) {
                *(float4*)&sW[kk][c] = *(const float4*)&Wa[(size_t)(k0 + kk) * 128 + c];
            } else {
#pragma unroll
                for (int j = 0; j < 4; j++) {
                    int cc = c + j;
                    sW[kk][cc] = (cc < 64) ? Wa[(size_t)(k0 + kk) * 64 + cc]
                                           : Wb[(size_t)(k0 + kk) * 64 + cc - 64];
                }
            }
        }
        __syncthreads();

#pragma unroll
        for (int kk = 0; kk < 8; kk++) {
            float xf[8], wf[8];
            *(float4*)&xf[0] = *(const float4*)&sX[kk][trow * 8];
            *(float4*)&xf[4] = *(const float4*)&sX[kk][trow * 8 + 4];
            *(float4*)&wf[0] = *(const float4*)&sW[kk][tcol * 8];
            *(float4*)&wf[4] = *(const float4*)&sW[kk][tcol * 8 + 4];
#pragma unroll
            for (int i = 0; i < 8; i++)
#pragma unroll
                for (int j = 0; j < 8; j++)
                    acc[i][j] += xf[i] * wf[j];
        }
        __syncthreads();
    }

#pragma unroll
    for (int i = 0; i < 8; i++) {
        int row = row0 + trow * 8 + i;
        if (row < n) {
            *(float4*)&Y[(size_t)row * CH + tcol * 8] =
                make_float4(acc[i][0], acc[i][1], acc[i][2], acc[i][3]);
            *(float4*)&Y[(size_t)row * CH + tcol * 8 + 4] =
                make_float4(acc[i][4], acc[i][5], acc[i][6], acc[i][7]);
        }
    }
}

// ---------------- layer-1 aggregation ----------------
// agg[i][c] = b1[c] + h1[i][c] * dinv[i]^2   (bias + self-loop)
__global__ void k_agg_init(const float* __restrict__ b1, int n) {
    int idx = blockIdx.x * blockDim.x + threadIdx.x;  // n*32 float4 chunks
    if (idx >= n * 32) return;
    int i = idx >> 5;
    int c = (idx & 31) * 4;
    float d = g_dinv[i];
    float s = d * d;
    float4 v  = *(const float4*)&g_h1[(size_t)i * CH + c];
    float4 bb = *(const float4*)&b1[c];
    float4 r  = make_float4(bb.x + v.x * s, bb.y + v.y * s,
                            bb.z + v.z * s, bb.w + v.w * s);
    *(float4*)&g_agg[(size_t)i * CH + c] = r;
}

// warp per edge: agg[dst] += h1[src] * dinv[src]*dinv[dst]
__global__ __launch_bounds__(256)
void k_agg_edge(const int* __restrict__ src, const int* __restrict__ dst, int E) {
    int w    = (blockIdx.x * blockDim.x + threadIdx.x) >> 5;
    int lane = threadIdx.x & 31;
    if (w >= E) return;
    int s = __ldg(&src[w]);
    int d = __ldg(&dst[w]);
    float coef = g_dinv[s] * g_dinv[d];
    float4 v = *(const float4*)&g_h1[(size_t)s * CH + lane * 4];
    v.x *= coef; v.y *= coef; v.z *= coef; v.w *= coef;
    red_add_v4(&g_agg[(size_t)d * CH + lane * 4], v);
}

// ---------------- relu + L2 row normalize: h1 = normalize(relu(agg)) ----------------
__global__ __launch_bounds__(256)
void k_norm(int n) {
    int row  = (blockIdx.x * blockDim.x + threadIdx.x) >> 5;
    int lane = threadIdx.x & 31;
    if (row >= n) return;
    float4 v = *(const float4*)&g_agg[(size_t)row * CH + lane * 4];
    v.x = fmaxf(v.x, 0.f); v.y = fmaxf(v.y, 0.f);
    v.z = fmaxf(v.z, 0.f); v.w = fmaxf(v.w, 0.f);
    float ss = v.x * v.x + v.y * v.y + v.z * v.z + v.w * v.w;
#pragma unroll
    for (int o = 16; o; o >>= 1) ss += __shfl_xor_sync(0xffffffffu, ss, o);
    float inv = 1.0f / fmaxf(sqrtf(ss), 1e-12f);
    v.x *= inv; v.y *= inv; v.z *= inv; v.w *= inv;
    *(float4*)&g_h1[(size_t)row * CH + lane * 4] = v;
}

// ---------------- layer-2 aggregation directly into d_out ----------------
// out layout: mu[n][64] then logstd[n][64]. g_agg holds [h@Wmu | h@Wls].
__global__ void k_out_init(const float* __restrict__ bmu,
                           const float* __restrict__ bls,
                           float* __restrict__ out, int n) {
    int idx = blockIdx.x * blockDim.x + threadIdx.x;  // n*32 float4 chunks
    if (idx >= n * 32) return;
    int i = idx >> 5;
    int c = (idx & 31) * 4;
    float d = g_dinv[i];
    float s = d * d;
    float4 v = *(const float4*)&g_agg[(size_t)i * CH + c];
    const float* b = (c < 64) ? (bmu + c) : (bls + c - 64);
    float4 bb = *(const float4*)b;
    float4 r  = make_float4(bb.x + v.x * s, bb.y + v.y * s,
                            bb.z + v.z * s, bb.w + v.w * s);
    float* o = (c < 64) ? (out + (size_t)i * 64 + c)
                        : (out + (size_t)n * 64 + (size_t)i * 64 + c - 64);
    *(float4*)o = r;
}

__global__ __launch_bounds__(256)
void k_out_edge(const int* __restrict__ src, const int* __restrict__ dst,
                float* __restrict__ out, int E, int n) {
    int w    = (blockIdx.x * blockDim.x + threadIdx.x) >> 5;
    int lane = threadIdx.x & 31;
    if (w >= E) return;
    int s = __ldg(&src[w]);
    int d = __ldg(&dst[w]);
    float coef = g_dinv[s] * g_dinv[d];
    int c = lane * 4;
    float4 v = *(const float4*)&g_agg[(size_t)s * CH + c];
    v.x *= coef; v.y *= coef; v.z *= coef; v.w *= coef;
    float* o = (c < 64) ? (out + (size_t)d * 64 + c)
                        : (out + (size_t)n * 64 + (size_t)d * 64 + c - 64);
    red_add_v4(o, v);
}

// ---------------- launch ----------------
extern "C" void kernel_launch(void* const* d_in, const int* in_sizes, int n_in,
                              void* d_out, int out_size) {
    const float* x   = (const float*)d_in[0];
    const int*   ei  = (const int*)d_in[1];
    const float* W1  = (const float*)d_in[2];
    const float* b1  = (const float*)d_in[3];
    const float* Wmu = (const float*)d_in[4];
    const float* bmu = (const float*)d_in[5];
    const float* Wls = (const float*)d_in[6];
    const float* bls = (const float*)d_in[7];

    int n = in_sizes[0] / CH;
    int E = in_sizes[1] / 2;
    const int* src = ei;
    const int* dst = ei + E;
    float* out = (float*)d_out;

    float *p_h1, *p_agg;
    cudaGetSymbolAddress((void**)&p_h1, g_h1);
    cudaGetSymbolAddress((void**)&p_agg, g_agg);

    // degree -> dinv
    k_deg_init<<<(n + 255) / 256, 256>>>(n);
    k_deg_count<<<(E + 255) / 256, 256>>>(dst, E);
    k_dinv<<<(n + 255) / 256, 256>>>(n);

    // layer 1: h1 = x @ W1
    k_gemm<<<(n + 127) / 128, 256>>>(x, W1, nullptr, p_h1, n);
    // agg = b1 + selfloop + scatter
    k_agg_init<<<(n * 32 + 255) / 256, 256>>>(b1, n);
    k_agg_edge<<<(E + 7) / 8, 256>>>(src, dst, E);
    // h1 = normalize(relu(agg))  (second relu is a no-op on non-negative data)
    k_norm<<<(n + 7) / 8, 256>>>(n);

    // layer 2: agg = h1 @ [Wmu | Wls]
    k_gemm<<<(n + 127) / 128, 256>>>(p_h1, Wmu, Wls, p_agg, n);
    // out = bias + selfloop + scatter (split mu / logstd layout)
    k_out_init<<<(n * 32 + 255) / 256, 256>>>(bmu, bls, out, n);
    k_out_edge<<<(E + 7) / 8, 256>>>(src, dst, out, E, n);
}

// round 2
// speedup vs baseline: 1.7924x; 1.7924x over previous
#include <cuda_runtime.h>
#include <math.h>

#define CH 128
#define NMAX 100000
#define EMAX 1600000

// ---------------- scratch (no allocations allowed) ----------------
__device__ int   g_deg[NMAX];
__device__ float g_dinv[NMAX];
__device__ int   g_off[NMAX + 1];
__device__ int   g_cur[NMAX];
__device__ int   g_esrc[EMAX];
__device__ int   g_bsum[512];
__device__ float g_h1[(size_t)NMAX * CH];
__device__ float g_agg[(size_t)NMAX * CH];

// ---------------- degree / dinv ----------------
__global__ void k_zero_deg(int n) {
    int i = blockIdx.x * blockDim.x + threadIdx.x;
    if (i < n) g_deg[i] = 0;
}

__global__ void k_count(const int* __restrict__ dst, int E) {
    int i = blockIdx.x * blockDim.x + threadIdx.x;
    if (i < E) atomicAdd(&g_deg[dst[i]], 1);
}

__global__ void k_dinv(int n) {
    int i = blockIdx.x * blockDim.x + threadIdx.x;
    if (i < n) g_dinv[i] = rsqrtf((float)(g_deg[i] + 1));  // +1 self loop
}

// ---------------- exclusive scan of g_deg -> g_off (chunk 1024/block) ----------------
__global__ __launch_bounds__(256)
void k_scan1(int n) {
    __shared__ int ssum[256];
    int b = blockIdx.x, t = threadIdx.x;
    int base = b * 1024 + t * 4;
    int v[4], s = 0;
#pragma unroll
    for (int j = 0; j < 4; j++) {
        v[j] = (base + j < n) ? g_deg[base + j] : 0;
        s += v[j];
    }
    ssum[t] = s;
    __syncthreads();
    // inclusive scan over 256 thread sums
    for (int off = 1; off < 256; off <<= 1) {
        int x = (t >= off) ? ssum[t - off] : 0;
        __syncthreads();
        ssum[t] += x;
        __syncthreads();
    }
    int excl = ssum[t] - s;
#pragma unroll
    for (int j = 0; j < 4; j++) {
        if (base + j < n) g_off[base + j] = excl;
        excl += v[j];
    }
    if (t == 255) g_bsum[b] = ssum[255];
}

__global__ void k_scan2(int nb) {
    if (threadIdx.x == 0) {
        int acc = 0;
        for (int i = 0; i < nb; i++) {
            int x = g_bsum[i];
            g_bsum[i] = acc;
            acc += x;
        }
    }
}

__global__ void k_scan3(int n, int E) {
    int i = blockIdx.x * blockDim.x + threadIdx.x;
    if (i < n) {
        int o = g_off[i] + g_bsum[i >> 10];
        g_off[i] = o;
        g_cur[i] = o;
    }
    if (i == 0) g_off[n] = E;
}

// ---------------- CSR fill ----------------
__global__ void k_fill(const int* __restrict__ src, const int* __restrict__ dst, int E) {
    int e = blockIdx.x * blockDim.x + threadIdx.x;
    if (e >= E) return;
    int d = dst[e];
    int pos = atomicAdd(&g_cur[d], 1);
    g_esrc[pos] = src[e];
}

// ---------------- SGEMM: Y[n x 128] = X[n x 128] @ W[128 x 128] ----------------
__global__ __launch_bounds__(256)
void k_gemm(const float* __restrict__ X,
            const float* __restrict__ Wa,
            const float* __restrict__ Wb,
            float* __restrict__ Y, int n) {
    __shared__ float sX[8][128];
    __shared__ float sW[8][128];

    int tid  = threadIdx.x;
    int tcol = tid & 15;
    int trow = tid >> 4;
    int row0 = blockIdx.x * 128;

    float acc[8][8];
#pragma unroll
    for (int i = 0; i < 8; i++)
#pragma unroll
        for (int j = 0; j < 8; j++) acc[i][j] = 0.0f;

    for (int k0 = 0; k0 < 128; k0 += 8) {
        {
            int r    = tid >> 1;
            int half = tid & 1;
            int row  = row0 + r;
            float4 v = make_float4(0.f, 0.f, 0.f, 0.f);
            if (row < n)
                v = *(const float4*)&X[(size_t)row * CH + k0 + half * 4];
            sX[half * 4 + 0][r] = v.x;
            sX[half * 4 + 1][r] = v.y;
            sX[half * 4 + 2][r] = v.z;
            sX[half * 4 + 3][r] = v.w;
        }
        {
            int idx = tid * 4;
            int kk  = idx >> 7;
            int c   = idx & 127;
            if (Wb == nullptr) {
                *(float4*)&sW[kk][c] = *(const float4*)&Wa[(size_t)(k0 + kk) * 128 + c];
            } else {
#pragma unroll
                for (int j = 0; j < 4; j++) {
                    int cc = c + j;
                    sW[kk][cc] = (cc < 64) ? Wa[(size_t)(k0 + kk) * 64 + cc]
                                           : Wb[(size_t)(k0 + kk) * 64 + cc - 64];
                }
            }
        }
        __syncthreads();

#pragma unroll
        for (int kk = 0; kk < 8; kk++) {
            float xf[8], wf[8];
            *(float4*)&xf[0] = *(const float4*)&sX[kk][trow * 8];
            *(float4*)&xf[4] = *(const float4*)&sX[kk][trow * 8 + 4];
            *(float4*)&wf[0] = *(const float4*)&sW[kk][tcol * 8];
            *(float4*)&wf[4] = *(const float4*)&sW[kk][tcol * 8 + 4];
#pragma unroll
            for (int i = 0; i < 8; i++)
#pragma unroll
                for (int j = 0; j < 8; j++)
                    acc[i][j] += xf[i] * wf[j];
        }
        __syncthreads();
    }

#pragma unroll
    for (int i = 0; i < 8; i++) {
        int row = row0 + trow * 8 + i;
        if (row < n) {
            *(float4*)&Y[(size_t)row * CH + tcol * 8] =
                make_float4(acc[i][0], acc[i][1], acc[i][2], acc[i][3]);
            *(float4*)&Y[(size_t)row * CH + tcol * 8 + 4] =
                make_float4(acc[i][4], acc[i][5], acc[i][6], acc[i][7]);
        }
    }
}

// ---------------- layer-1 gather + bias + relu + L2 normalize ----------------
// g_agg[d] = normalize(relu(b1 + dinv[d] * (dinv[d]*h1[d] + sum_{s} dinv[s]*h1[s])))
__global__ __launch_bounds__(256)
void k_gather_norm(const float* __restrict__ b1, int n) {
    int node = (blockIdx.x * blockDim.x + threadIdx.x) >> 5;
    int lane = threadIdx.x & 31;
    if (node >= n) return;
    int beg = g_off[node], end = g_off[node + 1];
    float dd = g_dinv[node];
    int c = lane * 4;

    // self-loop term: dinv[node]*h1[node]
    float4 acc = *(const float4*)&g_h1[(size_t)node * CH + c];
    acc.x *= dd; acc.y *= dd; acc.z *= dd; acc.w *= dd;

    int i = beg;
    for (; i + 4 <= end; i += 4) {
        int s0 = g_esrc[i], s1 = g_esrc[i + 1], s2 = g_esrc[i + 2], s3 = g_esrc[i + 3];
        float w0 = g_dinv[s0], w1 = g_dinv[s1], w2 = g_dinv[s2], w3 = g_dinv[s3];
        float4 v0 = *(const float4*)&g_h1[(size_t)s0 * CH + c];
        float4 v1 = *(const float4*)&g_h1[(size_t)s1 * CH + c];
        float4 v2 = *(const float4*)&g_h1[(size_t)s2 * CH + c];
        float4 v3 = *(const float4*)&g_h1[(size_t)s3 * CH + c];
        acc.x += w0 * v0.x + w1 * v1.x + w2 * v2.x + w3 * v3.x;
        acc.y += w0 * v0.y + w1 * v1.y + w2 * v2.y + w3 * v3.y;
        acc.z += w0 * v0.z + w1 * v1.z + w2 * v2.z + w3 * v3.z;
        acc.w += w0 * v0.w + w1 * v1.w + w2 * v2.w + w3 * v3.w;
    }
    for (; i < end; i++) {
        int s = g_esrc[i];
        float w = g_dinv[s];
        float4 v = *(const float4*)&g_h1[(size_t)s * CH + c];
        acc.x += w * v.x; acc.y += w * v.y; acc.z += w * v.z; acc.w += w * v.w;
    }

    float4 bb = *(const float4*)&b1[c];
    float4 r = make_float4(bb.x + dd * acc.x, bb.y + dd * acc.y,
                           bb.z + dd * acc.z, bb.w + dd * acc.w);
    r.x = fmaxf(r.x, 0.f); r.y = fmaxf(r.y, 0.f);
    r.z = fmaxf(r.z, 0.f); r.w = fmaxf(r.w, 0.f);
    float ss = r.x * r.x + r.y * r.y + r.z * r.z + r.w * r.w;
#pragma unroll
    for (int o = 16; o; o >>= 1) ss += __shfl_xor_sync(0xffffffffu, ss, o);
    float inv = 1.0f / fmaxf(sqrtf(ss), 1e-12f);
    r.x *= inv; r.y *= inv; r.z *= inv; r.w *= inv;
    *(float4*)&g_agg[(size_t)node * CH + c] = r;
}

// ---------------- layer-2 gather + bias, split mu/logstd into d_out ----------------
__global__ __launch_bounds__(256)
void k_gather_out(const float* __restrict__ bmu, const float* __restrict__ bls,
                  float* __restrict__ out, int n) {
    int node = (blockIdx.x * blockDim.x + threadIdx.x) >> 5;
    int lane = threadIdx.x & 31;
    if (node >= n) return;
    int beg = g_off[node], end = g_off[node + 1];
    float dd = g_dinv[node];
    int c = lane * 4;

    float4 acc = *(const float4*)&g_h1[(size_t)node * CH + c];
    acc.x *= dd; acc.y *= dd; acc.z *= dd; acc.w *= dd;

    int i = beg;
    for (; i + 4 <= end; i += 4) {
        int s0 = g_esrc[i], s1 = g_esrc[i + 1], s2 = g_esrc[i + 2], s3 = g_esrc[i + 3];
        float w0 = g_dinv[s0], w1 = g_dinv[s1], w2 = g_dinv[s2], w3 = g_dinv[s3];
        float4 v0 = *(const float4*)&g_h1[(size_t)s0 * CH + c];
        float4 v1 = *(const float4*)&g_h1[(size_t)s1 * CH + c];
        float4 v2 = *(const float4*)&g_h1[(size_t)s2 * CH + c];
        float4 v3 = *(const float4*)&g_h1[(size_t)s3 * CH + c];
        acc.x += w0 * v0.x + w1 * v1.x + w2 * v2.x + w3 * v3.x;
        acc.y += w0 * v0.y + w1 * v1.y + w2 * v2.y + w3 * v3.y;
        acc.z += w0 * v0.z + w1 * v1.z + w2 * v2.z + w3 * v3.z;
        acc.w += w0 * v0.w + w1 * v1.w + w2 * v2.w + w3 * v3.w;
    }
    for (; i < end; i++) {
        int s = g_esrc[i];
        float w = g_dinv[s];
        float4 v = *(const float4*)&g_h1[(size_t)s * CH + c];
        acc.x += w * v.x; acc.y += w * v.y; acc.z += w * v.z; acc.w += w * v.w;
    }

    const float* b = (c < 64) ? (bmu + c) : (bls + c - 64);
    float4 bb = *(const float4*)b;
    float4 r = make_float4(bb.x + dd * acc.x, bb.y + dd * acc.y,
                           bb.z + dd * acc.z, bb.w + dd * acc.w);
    float* o = (c < 64) ? (out + (size_t)node * 64 + c)
                        : (out + (size_t)n * 64 + (size_t)node * 64 + c - 64);
    *(float4*)o = r;
}

// ---------------- launch ----------------
extern "C" void kernel_launch(void* const* d_in, const int* in_sizes, int n_in,
                              void* d_out, int out_size) {
    const float* x   = (const float*)d_in[0];
    const int*   ei  = (const int*)d_in[1];
    const float* W1  = (const float*)d_in[2];
    const float* b1  = (const float*)d_in[3];
    const float* Wmu = (const float*)d_in[4];
    const float* bmu = (const float*)d_in[5];
    const float* Wls = (const float*)d_in[6];
    const float* bls = (const float*)d_in[7];

    int n = in_sizes[0] / CH;
    int E = in_sizes[1] / 2;
    const int* src = ei;
    const int* dst = ei + E;
    float* out = (float*)d_out;

    float *p_h1, *p_agg;
    cudaGetSymbolAddress((void**)&p_h1, g_h1);
    cudaGetSymbolAddress((void**)&p_agg, g_agg);

    int nb = (n + 1023) / 1024;

    // degree + dinv + CSR build
    k_zero_deg<<<(n + 255) / 256, 256>>>(n);
    k_count<<<(E + 255) / 256, 256>>>(dst, E);
    k_dinv<<<(n + 255) / 256, 256>>>(n);
    k_scan1<<<nb, 256>>>(n);
    k_scan2<<<1, 32>>>(nb);
    k_scan3<<<(n + 255) / 256, 256>>>(n, E);
    k_fill<<<(E + 255) / 256, 256>>>(src, dst, E);

    // layer 1: h1 = x @ W1; agg = normalize(relu(gcn_agg(h1) + b1))
    k_gemm<<<(n + 127) / 128, 256>>>(x, W1, nullptr, p_h1, n);
    k_gather_norm<<<(n * 32 + 255) / 256, 256>>>(b1, n);

    // layer 2: h1 = agg @ [Wmu | Wls]; out = gcn_agg(h1) + bias (split)
    k_gemm<<<(n + 127) / 128, 256>>>(p_agg, Wmu, Wls, p_h1, n);
    k_gather_out<<<(n * 32 + 255) / 256, 256>>>(bmu, bls, out, n);
}

// round 3
// speedup vs baseline: 2.7246x; 1.5201x over previous
#include <cuda_runtime.h>
#include <math.h>

#define CH 128
#define NMAX 100000
#define EMAX 1600000

// ---------------- scratch (no allocations allowed) ----------------
__device__ int   g_deg[NMAX];
__device__ float g_dinv[NMAX];
__device__ int   g_off[NMAX + 1];
__device__ int   g_cur[NMAX];
__device__ int   g_esrc[EMAX];
__device__ int   g_bsum[512];
__device__ float g_h1[(size_t)NMAX * CH];
__device__ float g_agg[(size_t)NMAX * CH];

// ---------------- degree / dinv ----------------
__global__ void k_zero_deg(int n) {
    int i = blockIdx.x * blockDim.x + threadIdx.x;
    if (i < n) g_deg[i] = 0;
}

__global__ void k_count(const int* __restrict__ dst, int E) {
    int i = blockIdx.x * blockDim.x + threadIdx.x;
    if (i < E) atomicAdd(&g_deg[dst[i]], 1);
}

__global__ void k_dinv(int n) {
    int i = blockIdx.x * blockDim.x + threadIdx.x;
    if (i < n) g_dinv[i] = rsqrtf((float)(g_deg[i] + 1));  // +1 self loop
}

// ---------------- exclusive scan of g_deg -> g_off ----------------
__global__ __launch_bounds__(256)
void k_scan1(int n) {
    __shared__ int ssum[256];
    int b = blockIdx.x, t = threadIdx.x;
    int base = b * 1024 + t * 4;
    int v[4], s = 0;
#pragma unroll
    for (int j = 0; j < 4; j++) {
        v[j] = (base + j < n) ? g_deg[base + j] : 0;
        s += v[j];
    }
    ssum[t] = s;
    __syncthreads();
    for (int off = 1; off < 256; off <<= 1) {
        int x = (t >= off) ? ssum[t - off] : 0;
        __syncthreads();
        ssum[t] += x;
        __syncthreads();
    }
    int excl = ssum[t] - s;
#pragma unroll
    for (int j = 0; j < 4; j++) {
        if (base + j < n) g_off[base + j] = excl;
        excl += v[j];
    }
    if (t == 255) g_bsum[b] = ssum[255];
}

__global__ void k_scan2(int nb) {
    if (threadIdx.x == 0) {
        int acc = 0;
        for (int i = 0; i < nb; i++) {
            int x = g_bsum[i];
            g_bsum[i] = acc;
            acc += x;
        }
    }
}

__global__ void k_scan3(int n, int E) {
    int i = blockIdx.x * blockDim.x + threadIdx.x;
    if (i < n) {
        int o = g_off[i] + g_bsum[i >> 10];
        g_off[i] = o;
        g_cur[i] = o;
    }
    if (i == 0) g_off[n] = E;
}

__global__ void k_fill(const int* __restrict__ src, const int* __restrict__ dst, int E) {
    int e = blockIdx.x * blockDim.x + threadIdx.x;
    if (e >= E) return;
    int d = dst[e];
    int pos = atomicAdd(&g_cur[d], 1);
    g_esrc[pos] = src[e];
}

// ---------------- tf32 helpers ----------------
__device__ __forceinline__ float to_tf32(float x) {
    float r;
    asm("cvt.rna.tf32.f32 %0, %1;" : "=f"(r) : "f"(x));
    return r;
}

__device__ __forceinline__ void mma_tf32(float* c, const unsigned* a,
                                         unsigned b0, unsigned b1) {
    asm volatile(
        "mma.sync.aligned.m16n8k8.row.col.f32.tf32.tf32.f32 "
        "{%0,%1,%2,%3}, {%4,%5,%6,%7}, {%8,%9}, {%0,%1,%2,%3};"
        : "+f"(c[0]), "+f"(c[1]), "+f"(c[2]), "+f"(c[3])
        : "r"(a[0]), "r"(a[1]), "r"(a[2]), "r"(a[3]), "r"(b0), "r"(b1));
}

// ---------------- tf32 tensor-core GEMM ----------------
// Y[n x 128] = X[n x 128] @ W[128 x 128], W = Wa (full) or [Wa|Wb] (64+64 cols).
// Block: 256 thr, 128x128 tile. Warps 4(m) x 2(n); warp tile 32x64.
// smem k-major, pad 132 for conflict-free fragment loads.
__global__ __launch_bounds__(256)
void k_gemm_tf32(const float* __restrict__ X,
                 const float* __restrict__ Wa,
                 const float* __restrict__ Wb,
                 float* __restrict__ Y, int n) {
    __shared__ float sA[32][132];  // sA[k][m]
    __shared__ float sB[32][132];  // sB[k][n]

    int tid  = threadIdx.x;
    int warp = tid >> 5;
    int lane = tid & 31;
    int wm   = warp >> 1;   // 0..3
    int wn   = warp & 1;    // 0..1
    int ar   = lane >> 2;   // groupID 0..7
    int ac   = lane & 3;    // tid_in_group 0..3
    int row0 = blockIdx.x * 128;

    float c[2][8][4];
#pragma unroll
    for (int mt = 0; mt < 2; mt++)
#pragma unroll
        for (int nt = 0; nt < 8; nt++)
#pragma unroll
            for (int j = 0; j < 4; j++) c[mt][nt][j] = 0.0f;

    for (int k0 = 0; k0 < 128; k0 += 32) {
        // X chunk: 128 rows x 32 k -> sA[k][m] (transposed), tf32-rounded
#pragma unroll
        for (int it = 0; it < 4; it++) {
            int idx = tid + it * 256;       // 0..1023
            int m   = idx >> 3;             // 0..127
            int kk  = (idx & 7) * 4;        // 0..28
            int row = row0 + m;
            float4 v = make_float4(0.f, 0.f, 0.f, 0.f);
            if (row < n)
                v = *(const float4*)&X[(size_t)row * CH + k0 + kk];
            sA[kk + 0][m] = to_tf32(v.x);
            sA[kk + 1][m] = to_tf32(v.y);
            sA[kk + 2][m] = to_tf32(v.z);
            sA[kk + 3][m] = to_tf32(v.w);
        }
        // W chunk: 32 k x 128 n -> sB[k][n], tf32-rounded
#pragma unroll
        for (int it = 0; it < 4; it++) {
            int idx = tid + it * 256;       // 0..1023
            int kk  = idx >> 5;             // 0..31
            int nn  = (idx & 31) * 4;       // 0..124
            float4 v;
            if (Wb == nullptr) {
                v = *(const float4*)&Wa[(size_t)(k0 + kk) * 128 + nn];
            } else {
                const float* p = (nn < 64) ? &Wa[(size_t)(k0 + kk) * 64 + nn]
                                           : &Wb[(size_t)(k0 + kk) * 64 + nn - 64];
                v = *(const float4*)p;
            }
            float4 t = make_float4(to_tf32(v.x), to_tf32(v.y),
                                   to_tf32(v.z), to_tf32(v.w));
            *(float4*)&sB[kk][nn] = t;
        }
        __syncthreads();

#pragma unroll
        for (int ks = 0; ks < 32; ks += 8) {
            unsigned a[2][4];
#pragma unroll
            for (int mt = 0; mt < 2; mt++) {
                int m = wm * 32 + mt * 16;
                a[mt][0] = __float_as_uint(sA[ks + ac][m + ar]);
                a[mt][1] = __float_as_uint(sA[ks + ac][m + ar + 8]);
                a[mt][2] = __float_as_uint(sA[ks + ac + 4][m + ar]);
                a[mt][3] = __float_as_uint(sA[ks + ac + 4][m + ar + 8]);
            }
#pragma unroll
            for (int nt = 0; nt < 8; nt++) {
                int nb = wn * 64 + nt * 8;
                unsigned b0 = __float_as_uint(sB[ks + ac][nb + ar]);
                unsigned b1 = __float_as_uint(sB[ks + ac + 4][nb + ar]);
                mma_tf32(c[0][nt], a[0], b0, b1);
                mma_tf32(c[1][nt], a[1], b0, b1);
            }
        }
        __syncthreads();
    }

    // epilogue: c[mt][nt][j] -> Y
#pragma unroll
    for (int mt = 0; mt < 2; mt++) {
        int rbase = row0 + wm * 32 + mt * 16 + ar;
#pragma unroll
        for (int half = 0; half < 2; half++) {
            int row = rbase + half * 8;
            if (row >= n) continue;
#pragma unroll
            for (int nt = 0; nt < 8; nt++) {
                int col = wn * 64 + nt * 8 + ac * 2;
                float2 v = make_float2(c[mt][nt][half * 2],
                                       c[mt][nt][half * 2 + 1]);
                *(float2*)&Y[(size_t)row * CH + col] = v;
            }
        }
    }
}

// ---------------- layer-1 gather + bias + relu + L2 normalize ----------------
__global__ __launch_bounds__(256)
void k_gather_norm(const float* __restrict__ b1, int n) {
    int node = (blockIdx.x * blockDim.x + threadIdx.x) >> 5;
    int lane = threadIdx.x & 31;
    if (node >= n) return;
    int beg = g_off[node], end = g_off[node + 1];
    float dd = g_dinv[node];
    int c = lane * 4;

    float4 acc = *(const float4*)&g_h1[(size_t)node * CH + c];
    acc.x *= dd; acc.y *= dd; acc.z *= dd; acc.w *= dd;

    int i = beg;
    for (; i + 4 <= end; i += 4) {
        int s0 = g_esrc[i], s1 = g_esrc[i + 1], s2 = g_esrc[i + 2], s3 = g_esrc[i + 3];
        float w0 = g_dinv[s0], w1 = g_dinv[s1], w2 = g_dinv[s2], w3 = g_dinv[s3];
        float4 v0 = *(const float4*)&g_h1[(size_t)s0 * CH + c];
        float4 v1 = *(const float4*)&g_h1[(size_t)s1 * CH + c];
        float4 v2 = *(const float4*)&g_h1[(size_t)s2 * CH + c];
        float4 v3 = *(const float4*)&g_h1[(size_t)s3 * CH + c];
        acc.x += w0 * v0.x + w1 * v1.x + w2 * v2.x + w3 * v3.x;
        acc.y += w0 * v0.y + w1 * v1.y + w2 * v2.y + w3 * v3.y;
        acc.z += w0 * v0.z + w1 * v1.z + w2 * v2.z + w3 * v3.z;
        acc.w += w0 * v0.w + w1 * v1.w + w2 * v2.w + w3 * v3.w;
    }
    for (; i < end; i++) {
        int s = g_esrc[i];
        float w = g_dinv[s];
        float4 v = *(const float4*)&g_h1[(size_t)s * CH + c];
        acc.x += w * v.x; acc.y += w * v.y; acc.z += w * v.z; acc.w += w * v.w;
    }

    float4 bb = *(const float4*)&b1[c];
    float4 r = make_float4(bb.x + dd * acc.x, bb.y + dd * acc.y,
                           bb.z + dd * acc.z, bb.w + dd * acc.w);
    r.x = fmaxf(r.x, 0.f); r.y = fmaxf(r.y, 0.f);
    r.z = fmaxf(r.z, 0.f); r.w = fmaxf(r.w, 0.f);
    float ss = r.x * r.x + r.y * r.y + r.z * r.z + r.w * r.w;
#pragma unroll
    for (int o = 16; o; o >>= 1) ss += __shfl_xor_sync(0xffffffffu, ss, o);
    float inv = 1.0f / fmaxf(sqrtf(ss), 1e-12f);
    r.x *= inv; r.y *= inv; r.z *= inv; r.w *= inv;
    *(float4*)&g_agg[(size_t)node * CH + c] = r;
}

// ---------------- layer-2 gather + bias, split mu/logstd into d_out ----------------
__global__ __launch_bounds__(256)
void k_gather_out(const float* __restrict__ bmu, const float* __restrict__ bls,
                  float* __restrict__ out, int n) {
    int node = (blockIdx.x * blockDim.x + threadIdx.x) >> 5;
    int lane = threadIdx.x & 31;
    if (node >= n) return;
    int beg = g_off[node], end = g_off[node + 1];
    float dd = g_dinv[node];
    int c = lane * 4;

    float4 acc = *(const float4*)&g_h1[(size_t)node * CH + c];
    acc.x *= dd; acc.y *= dd; acc.z *= dd; acc.w *= dd;

    int i = beg;
    for (; i + 4 <= end; i += 4) {
        int s0 = g_esrc[i], s1 = g_esrc[i + 1], s2 = g_esrc[i + 2], s3 = g_esrc[i + 3];
        float w0 = g_dinv[s0], w1 = g_dinv[s1], w2 = g_dinv[s2], w3 = g_dinv[s3];
        float4 v0 = *(const float4*)&g_h1[(size_t)s0 * CH + c];
        float4 v1 = *(const float4*)&g_h1[(size_t)s1 * CH + c];
        float4 v2 = *(const float4*)&g_h1[(size_t)s2 * CH + c];
        float4 v3 = *(const float4*)&g_h1[(size_t)s3 * CH + c];
        acc.x += w0 * v0.x + w1 * v1.x + w2 * v2.x + w3 * v3.x;
        acc.y += w0 * v0.y + w1 * v1.y + w2 * v2.y + w3 * v3.y;
        acc.z += w0 * v0.z + w1 * v1.z + w2 * v2.z + w3 * v3.z;
        acc.w += w0 * v0.w + w1 * v1.w + w2 * v2.w + w3 * v3.w;
    }
    for (; i < end; i++) {
        int s = g_esrc[i];
        float w = g_dinv[s];
        float4 v = *(const float4*)&g_h1[(size_t)s * CH + c];
        acc.x += w * v.x; acc.y += w * v.y; acc.z += w * v.z; acc.w += w * v.w;
    }

    const float* b = (c < 64) ? (bmu + c) : (bls + c - 64);
    float4 bb = *(const float4*)b;
    float4 r = make_float4(bb.x + dd * acc.x, bb.y + dd * acc.y,
                           bb.z + dd * acc.z, bb.w + dd * acc.w);
    float* o = (c < 64) ? (out + (size_t)node * 64 + c)
                        : (out + (size_t)n * 64 + (size_t)node * 64 + c - 64);
    *(float4*)o = r;
}

// ---------------- launch ----------------
extern "C" void kernel_launch(void* const* d_in, const int* in_sizes, int n_in,
                              void* d_out, int out_size) {
    const float* x   = (const float*)d_in[0];
    const int*   ei  = (const int*)d_in[1];
    const float* W1  = (const float*)d_in[2];
    const float* b1  = (const float*)d_in[3];
    const float* Wmu = (const float*)d_in[4];
    const float* bmu = (const float*)d_in[5];
    const float* Wls = (const float*)d_in[6];
    const float* bls = (const float*)d_in[7];

    int n = in_sizes[0] / CH;
    int E = in_sizes[1] / 2;
    const int* src = ei;
    const int* dst = ei + E;
    float* out = (float*)d_out;

    float *p_h1, *p_agg;
    cudaGetSymbolAddress((void**)&p_h1, g_h1);
    cudaGetSymbolAddress((void**)&p_agg, g_agg);

    int nb = (n + 1023) / 1024;

    // degree + dinv + CSR build
    k_zero_deg<<<(n + 255) / 256, 256>>>(n);
    k_count<<<(E + 255) / 256, 256>>>(dst, E);
    k_dinv<<<(n + 255) / 256, 256>>>(n);
    k_scan1<<<nb, 256>>>(n);
    k_scan2<<<1, 32>>>(nb);
    k_scan3<<<(n + 255) / 256, 256>>>(n, E);
    k_fill<<<(E + 255) / 256, 256>>>(src, dst, E);

    // layer 1: h1 = x @ W1; agg = normalize(relu(gcn_agg(h1) + b1))
    k_gemm_tf32<<<(n + 127) / 128, 256>>>(x, W1, nullptr, p_h1, n);
    k_gather_norm<<<(n * 32 + 255) / 256, 256>>>(b1, n);

    // layer 2: h1 = agg @ [Wmu | Wls]; out = gcn_agg(h1) + bias (split)
    k_gemm_tf32<<<(n + 127) / 128, 256>>>(p_agg, Wmu, Wls, p_h1, n);
    k_gather_out<<<(n * 32 + 255) / 256, 256>>>(bmu, bls, out, n);
}

// round 4
// speedup vs baseline: 2.8142x; 1.0329x over previous
#include <cuda_runtime.h>
#include <cuda_fp16.h>
#include <math.h>

#define CH 128
#define NMAX 100000
#define EMAX 1600000

// ---------------- scratch (no allocations allowed) ----------------
__device__ int    g_deg[NMAX];
__device__ float  g_dinv[NMAX];
__device__ int    g_off[NMAX + 1];
__device__ int    g_cur[NMAX];
__device__ int    g_esrc[EMAX];
__device__ int    g_bsum[512];
__device__ __half g_hh[(size_t)NMAX * CH];   // fp16 gather source (GEMM outputs)
__device__ float  g_agg[(size_t)NMAX * CH];  // fp32 normalized hidden (GEMM2 input)

// ---------------- degree / dinv ----------------
__global__ void k_zero_deg(int n) {
    int i = blockIdx.x * blockDim.x + threadIdx.x;
    if (i < n) g_deg[i] = 0;
}

__global__ void k_count(const int* __restrict__ dst, int E) {
    int i = blockIdx.x * blockDim.x + threadIdx.x;
    if (i < E) atomicAdd(&g_deg[dst[i]], 1);
}

__global__ void k_dinv(int n) {
    int i = blockIdx.x * blockDim.x + threadIdx.x;
    if (i < n) g_dinv[i] = rsqrtf((float)(g_deg[i] + 1));  // +1 self loop
}

// ---------------- exclusive scan of g_deg -> g_off ----------------
__global__ __launch_bounds__(256)
void k_scan1(int n) {
    __shared__ int ssum[256];
    int b = blockIdx.x, t = threadIdx.x;
    int base = b * 1024 + t * 4;
    int v[4], s = 0;
#pragma unroll
    for (int j = 0; j < 4; j++) {
        v[j] = (base + j < n) ? g_deg[base + j] : 0;
        s += v[j];
    }
    ssum[t] = s;
    __syncthreads();
    for (int off = 1; off < 256; off <<= 1) {
        int x = (t >= off) ? ssum[t - off] : 0;
        __syncthreads();
        ssum[t] += x;
        __syncthreads();
    }
    int excl = ssum[t] - s;
#pragma unroll
    for (int j = 0; j < 4; j++) {
        if (base + j < n) g_off[base + j] = excl;
        excl += v[j];
    }
    if (t == 255) g_bsum[b] = ssum[255];
}

__global__ void k_scan2(int nb) {
    if (threadIdx.x == 0) {
        int acc = 0;
        for (int i = 0; i < nb; i++) {
            int x = g_bsum[i];
            g_bsum[i] = acc;
            acc += x;
        }
    }
}

__global__ void k_scan3(int n, int E) {
    int i = blockIdx.x * blockDim.x + threadIdx.x;
    if (i < n) {
        int o = g_off[i] + g_bsum[i >> 10];
        g_off[i] = o;
        g_cur[i] = o;
    }
    if (i == 0) g_off[n] = E;
}

__global__ void k_fill(const int* __restrict__ src, const int* __restrict__ dst, int E) {
    int e = blockIdx.x * blockDim.x + threadIdx.x;
    if (e >= E) return;
    int d = dst[e];
    int pos = atomicAdd(&g_cur[d], 1);
    g_esrc[pos] = src[e];
}

// ---------------- tf32 helpers ----------------
__device__ __forceinline__ float to_tf32(float x) {
    float r;
    asm("cvt.rna.tf32.f32 %0, %1;" : "=f"(r) : "f"(x));
    return r;
}

__device__ __forceinline__ void mma_tf32(float* c, const unsigned* a,
                                         unsigned b0, unsigned b1) {
    asm volatile(
        "mma.sync.aligned.m16n8k8.row.col.f32.tf32.tf32.f32 "
        "{%0,%1,%2,%3}, {%4,%5,%6,%7}, {%8,%9}, {%0,%1,%2,%3};"
        : "+f"(c[0]), "+f"(c[1]), "+f"(c[2]), "+f"(c[3])
        : "r"(a[0]), "r"(a[1]), "r"(a[2]), "r"(a[3]), "r"(b0), "r"(b1));
}

// ---------------- tf32 tensor-core GEMM, fp16 output ----------------
// Yh[n x 128] (half) = X[n x 128] @ W[128 x 128]; W = Wa or [Wa|Wb].
__global__ __launch_bounds__(256)
void k_gemm_tf32(const float* __restrict__ X,
                 const float* __restrict__ Wa,
                 const float* __restrict__ Wb,
                 __half2* __restrict__ Yh, int n) {
    __shared__ float sA[32][132];  // sA[k][m]
    __shared__ float sB[32][132];  // sB[k][n]

    int tid  = threadIdx.x;
    int warp = tid >> 5;
    int lane = tid & 31;
    int wm   = warp >> 1;
    int wn   = warp & 1;
    int ar   = lane >> 2;
    int ac   = lane & 3;
    int row0 = blockIdx.x * 128;

    float c[2][8][4];
#pragma unroll
    for (int mt = 0; mt < 2; mt++)
#pragma unroll
        for (int nt = 0; nt < 8; nt++)
#pragma unroll
            for (int j = 0; j < 4; j++) c[mt][nt][j] = 0.0f;

    for (int k0 = 0; k0 < 128; k0 += 32) {
#pragma unroll
        for (int it = 0; it < 4; it++) {
            int idx = tid + it * 256;
            int m   = idx >> 3;
            int kk  = (idx & 7) * 4;
            int row = row0 + m;
            float4 v = make_float4(0.f, 0.f, 0.f, 0.f);
            if (row < n)
                v = *(const float4*)&X[(size_t)row * CH + k0 + kk];
            sA[kk + 0][m] = to_tf32(v.x);
            sA[kk + 1][m] = to_tf32(v.y);
            sA[kk + 2][m] = to_tf32(v.z);
            sA[kk + 3][m] = to_tf32(v.w);
        }
#pragma unroll
        for (int it = 0; it < 4; it++) {
            int idx = tid + it * 256;
            int kk  = idx >> 5;
            int nn  = (idx & 31) * 4;
            float4 v;
            if (Wb == nullptr) {
                v = *(const float4*)&Wa[(size_t)(k0 + kk) * 128 + nn];
            } else {
                const float* p = (nn < 64) ? &Wa[(size_t)(k0 + kk) * 64 + nn]
                                           : &Wb[(size_t)(k0 + kk) * 64 + nn - 64];
                v = *(const float4*)p;
            }
            float4 t = make_float4(to_tf32(v.x), to_tf32(v.y),
                                   to_tf32(v.z), to_tf32(v.w));
            *(float4*)&sB[kk][nn] = t;
        }
        __syncthreads();

#pragma unroll
        for (int ks = 0; ks < 32; ks += 8) {
            unsigned a[2][4];
#pragma unroll
            for (int mt = 0; mt < 2; mt++) {
                int m = wm * 32 + mt * 16;
                a[mt][0] = __float_as_uint(sA[ks + ac][m + ar]);
                a[mt][1] = __float_as_uint(sA[ks + ac][m + ar + 8]);
                a[mt][2] = __float_as_uint(sA[ks + ac + 4][m + ar]);
                a[mt][3] = __float_as_uint(sA[ks + ac + 4][m + ar + 8]);
            }
#pragma unroll
            for (int nt = 0; nt < 8; nt++) {
                int nb = wn * 64 + nt * 8;
                unsigned b0 = __float_as_uint(sB[ks + ac][nb + ar]);
                unsigned b1 = __float_as_uint(sB[ks + ac + 4][nb + ar]);
                mma_tf32(c[0][nt], a[0], b0, b1);
                mma_tf32(c[1][nt], a[1], b0, b1);
            }
        }
        __syncthreads();
    }

#pragma unroll
    for (int mt = 0; mt < 2; mt++) {
        int rbase = row0 + wm * 32 + mt * 16 + ar;
#pragma unroll
        for (int half = 0; half < 2; half++) {
            int row = rbase + half * 8;
            if (row >= n) continue;
#pragma unroll
            for (int nt = 0; nt < 8; nt++) {
                int col = wn * 64 + nt * 8 + ac * 2;
                Yh[(size_t)row * 64 + (col >> 1)] =
                    __floats2half2_rn(c[mt][nt][half * 2],
                                      c[mt][nt][half * 2 + 1]);
            }
        }
    }
}

// ---------------- fp16 row load helper: 4 halves per lane ----------------
struct F4 { float a, b, c, d; };
__device__ __forceinline__ F4 load_h4(const __half2* base, int row, int lane2) {
    // lane2 = lane*2 (half2 units); 8-byte load
    uint2 u = *(const uint2*)&base[(size_t)row * 64 + lane2];
    __half2 h0 = *(__half2*)&u.x;
    __half2 h1 = *(__half2*)&u.y;
    float2 f0 = __half22float2(h0);
    float2 f1 = __half22float2(h1);
    F4 r; r.a = f0.x; r.b = f0.y; r.c = f1.x; r.d = f1.y;
    return r;
}

// ---------------- layer-1 gather (fp16 src) + bias + relu + L2 normalize ----------------
__global__ __launch_bounds__(256)
void k_gather_norm(const float* __restrict__ b1, int n) {
    int node = (blockIdx.x * blockDim.x + threadIdx.x) >> 5;
    int lane = threadIdx.x & 31;
    if (node >= n) return;
    int beg = g_off[node], end = g_off[node + 1];
    float dd = g_dinv[node];
    int c = lane * 4;
    int lane2 = lane * 2;
    const __half2* H = (const __half2*)g_hh;

    F4 sv = load_h4(H, node, lane2);
    float ax = dd * sv.a, ay = dd * sv.b, az = dd * sv.c, aw = dd * sv.d;

    int i = beg;
    for (; i + 4 <= end; i += 4) {
        int s0 = g_esrc[i], s1 = g_esrc[i + 1], s2 = g_esrc[i + 2], s3 = g_esrc[i + 3];
        float w0 = g_dinv[s0], w1 = g_dinv[s1], w2 = g_dinv[s2], w3 = g_dinv[s3];
        F4 v0 = load_h4(H, s0, lane2);
        F4 v1 = load_h4(H, s1, lane2);
        F4 v2 = load_h4(H, s2, lane2);
        F4 v3 = load_h4(H, s3, lane2);
        ax += w0 * v0.a + w1 * v1.a + w2 * v2.a + w3 * v3.a;
        ay += w0 * v0.b + w1 * v1.b + w2 * v2.b + w3 * v3.b;
        az += w0 * v0.c + w1 * v1.c + w2 * v2.c + w3 * v3.c;
        aw += w0 * v0.d + w1 * v1.d + w2 * v2.d + w3 * v3.d;
    }
    for (; i < end; i++) {
        int s = g_esrc[i];
        float w = g_dinv[s];
        F4 v = load_h4(H, s, lane2);
        ax += w * v.a; ay += w * v.b; az += w * v.c; aw += w * v.d;
    }

    float4 bb = *(const float4*)&b1[c];
    float4 r = make_float4(bb.x + dd * ax, bb.y + dd * ay,
                           bb.z + dd * az, bb.w + dd * aw);
    r.x = fmaxf(r.x, 0.f); r.y = fmaxf(r.y, 0.f);
    r.z = fmaxf(r.z, 0.f); r.w = fmaxf(r.w, 0.f);
    float ss = r.x * r.x + r.y * r.y + r.z * r.z + r.w * r.w;
#pragma unroll
    for (int o = 16; o; o >>= 1) ss += __shfl_xor_sync(0xffffffffu, ss, o);
    float inv = 1.0f / fmaxf(sqrtf(ss), 1e-12f);
    r.x *= inv; r.y *= inv; r.z *= inv; r.w *= inv;
    *(float4*)&g_agg[(size_t)node * CH + c] = r;
}

// ---------------- layer-2 gather (fp16 src) + bias, split mu/logstd ----------------
__global__ __launch_bounds__(256)
void k_gather_out(const float* __restrict__ bmu, const float* __restrict__ bls,
                  float* __restrict__ out, int n) {
    int node = (blockIdx.x * blockDim.x + threadIdx.x) >> 5;
    int lane = threadIdx.x & 31;
    if (node >= n) return;
    int beg = g_off[node], end = g_off[node + 1];
    float dd = g_dinv[node];
    int c = lane * 4;
    int lane2 = lane * 2;
    const __half2* H = (const __half2*)g_hh;

    F4 sv = load_h4(H, node, lane2);
    float ax = dd * sv.a, ay = dd * sv.b, az = dd * sv.c, aw = dd * sv.d;

    int i = beg;
    for (; i + 4 <= end; i += 4) {
        int s0 = g_esrc[i], s1 = g_esrc[i + 1], s2 = g_esrc[i + 2], s3 = g_esrc[i + 3];
        float w0 = g_dinv[s0], w1 = g_dinv[s1], w2 = g_dinv[s2], w3 = g_dinv[s3];
        F4 v0 = load_h4(H, s0, lane2);
        F4 v1 = load_h4(H, s1, lane2);
        F4 v2 = load_h4(H, s2, lane2);
        F4 v3 = load_h4(H, s3, lane2);
        ax += w0 * v0.a + w1 * v1.a + w2 * v2.a + w3 * v3.a;
        ay += w0 * v0.b + w1 * v1.b + w2 * v2.b + w3 * v3.b;
        az += w0 * v0.c + w1 * v1.c + w2 * v2.c + w3 * v3.c;
        aw += w0 * v0.d + w1 * v1.d + w2 * v2.d + w3 * v3.d;
    }
    for (; i < end; i++) {
        int s = g_esrc[i];
        float w = g_dinv[s];
        F4 v = load_h4(H, s, lane2);
        ax += w * v.a; ay += w * v.b; az += w * v.c; aw += w * v.d;
    }

    const float* b = (c < 64) ? (bmu + c) : (bls + c - 64);
    float4 bb = *(const float4*)b;
    float4 r = make_float4(bb.x + dd * ax, bb.y + dd * ay,
                           bb.z + dd * az, bb.w + dd * aw);
    float* o = (c < 64) ? (out + (size_t)node * 64 + c)
                        : (out + (size_t)n * 64 + (size_t)node * 64 + c - 64);
    *(float4*)o = r;
}

// ---------------- launch ----------------
extern "C" void kernel_launch(void* const* d_in, const int* in_sizes, int n_in,
                              void* d_out, int out_size) {
    const float* x   = (const float*)d_in[0];
    const int*   ei  = (const int*)d_in[1];
    const float* W1  = (const float*)d_in[2];
    const float* b1  = (const float*)d_in[3];
    const float* Wmu = (const float*)d_in[4];
    const float* bmu = (const float*)d_in[5];
    const float* Wls = (const float*)d_in[6];
    const float* bls = (const float*)d_in[7];

    int n = in_sizes[0] / CH;
    int E = in_sizes[1] / 2;
    const int* src = ei;
    const int* dst = ei + E;
    float* out = (float*)d_out;

    __half2* p_hh;
    float*   p_agg;
    cudaGetSymbolAddress((void**)&p_hh, g_hh);
    cudaGetSymbolAddress((void**)&p_agg, g_agg);

    int nb = (n + 1023) / 1024;

    // degree + dinv + CSR build
    k_zero_deg<<<(n + 255) / 256, 256>>>(n);
    k_count<<<(E + 255) / 256, 256>>>(dst, E);
    k_dinv<<<(n + 255) / 256, 256>>>(n);
    k_scan1<<<nb, 256>>>(n);
    k_scan2<<<1, 32>>>(nb);
    k_scan3<<<(n + 255) / 256, 256>>>(n, E);
    k_fill<<<(E + 255) / 256, 256>>>(src, dst, E);

    // layer 1
    k_gemm_tf32<<<(n + 127) / 128, 256>>>(x, W1, nullptr, p_hh, n);
    k_gather_norm<<<(n * 32 + 255) / 256, 256>>>(b1, n);

    // layer 2
    k_gemm_tf32<<<(n + 127) / 128, 256>>>(p_agg, Wmu, Wls, p_hh, n);
    k_gather_out<<<(n * 32 + 255) / 256, 256>>>(bmu, bls, out, n);
}